// round 1
// baseline (speedup 1.0000x reference)
#include <cuda_runtime.h>
#include <cuda_bf16.h>

#define Bb   4
#define Nn   2048
#define BN   (Bb*Nn)      // 8192
#define DIM  64
#define FIN  32
#define HEADS 4
#define DH   16
#define MAXD 384
#define SCALE 0.25f

// ---------------- device scratch (static, allocation-free) ----------------
__device__ float g_q[BN*DIM];
__device__ float g_k[BN*DIM];
__device__ float g_v[BN*DIM];
__device__ float g_o[BN*DIM];
__device__ unsigned short g_nbr[(size_t)BN*MAXD];
__device__ int g_cnt[BN];

// ---------------- 1) adjacency -> neighbor lists (once) ----------------
__global__ void build_nbr_kernel(const float* __restrict__ adj) {
    int warp = blockIdx.x * (blockDim.x >> 5) + (threadIdx.x >> 5);
    if (warp >= BN) return;
    int lane = threadIdx.x & 31;
    const float* a = adj + (size_t)warp * Nn;
    unsigned short* nb = g_nbr + (size_t)warp * MAXD;
    int cnt = 0;
    for (int j0 = 0; j0 < Nn; j0 += 32) {
        float v = a[j0 + lane];
        unsigned m = __ballot_sync(0xffffffffu, v > 0.f);
        if (v > 0.f) {
            int pos = cnt + __popc(m & ((1u << lane) - 1u));
            if (pos < MAXD) nb[pos] = (unsigned short)(j0 + lane);
        }
        cnt += __popc(m);
    }
    if (lane == 0) g_cnt[warp] = min(cnt, MAXD);
}

// ---------------- 2) fc: x = relu(nf @ W_fc + b_fc) ----------------
__global__ void fc_kernel(const float* __restrict__ nf,
                          const float* __restrict__ W,
                          const float* __restrict__ b,
                          float* __restrict__ x) {
    int idx = blockIdx.x * blockDim.x + threadIdx.x;   // BN*64
    if (idx >= BN * DIM) return;
    int row = idx >> 6, o = idx & 63;
    const float* nr = nf + (size_t)row * FIN;
    float acc = __ldg(b + o);
    #pragma unroll
    for (int i = 0; i < FIN; i++) acc += nr[i] * __ldg(W + i * DIM + o);
    x[idx] = fmaxf(acc, 0.f);
}

// ---------------- 3) LN + QKV projections (16 rows / block, 192 thr) ----------------
__global__ void ln_qkv_kernel(const float* __restrict__ x,
                              const float* __restrict__ lng,
                              const float* __restrict__ lnb,
                              const float* __restrict__ Wq,
                              const float* __restrict__ bq,
                              const float* __restrict__ Wkv,
                              const float* __restrict__ bkv) {
    __shared__ float hs[16][DIM];
    __shared__ float mu_s[16], rs_s[16];
    int tid = threadIdx.x;                 // 192
    int row0 = blockIdx.x * 16;

    // load 16 rows of x (1024 floats) as float4
    const float4* xv = (const float4*)(x + (size_t)row0 * DIM);
    float4* hv = (float4*)&hs[0][0];
    for (int i = tid; i < 16 * 16; i += 192) hv[i] = xv[i];
    __syncthreads();

    if (tid < 16) {
        float m = 0.f;
        #pragma unroll
        for (int j = 0; j < DIM; j++) m += hs[tid][j];
        m *= (1.f / DIM);
        float v = 0.f;
        #pragma unroll
        for (int j = 0; j < DIM; j++) { float d = hs[tid][j] - m; v += d * d; }
        v *= (1.f / DIM);
        mu_s[tid] = m;
        rs_s[tid] = rsqrtf(v + 1e-5f);
    }
    __syncthreads();
    for (int i = tid; i < 16 * DIM; i += 192) {
        int r = i >> 6, c = i & 63;
        hs[r][c] = (hs[r][c] - mu_s[r]) * rs_s[r] * __ldg(lng + c) + __ldg(lnb + c);
    }
    __syncthreads();

    // each thread owns one output column o of [q(64) | k(64) | v(64)]
    int o = tid;
    const float* wp; int ws; float bias; float* outp;
    if (o < 64)       { wp = Wq + o;          ws = 64;  bias = __ldg(bq + o);        outp = g_q + o; }
    else if (o < 128) { wp = Wkv + (o - 64);  ws = 128; bias = __ldg(bkv + (o - 64)); outp = g_k + (o - 64); }
    else              { wp = Wkv + (o - 64);  ws = 128; bias = __ldg(bkv + (o - 64)); outp = g_v + (o - 128); }

    float acc[16];
    #pragma unroll
    for (int r = 0; r < 16; r++) acc[r] = bias;

    for (int in4 = 0; in4 < 16; in4++) {
        float w0 = __ldg(wp + (4 * in4 + 0) * ws);
        float w1 = __ldg(wp + (4 * in4 + 1) * ws);
        float w2 = __ldg(wp + (4 * in4 + 2) * ws);
        float w3 = __ldg(wp + (4 * in4 + 3) * ws);
        #pragma unroll
        for (int r = 0; r < 16; r++) {
            float4 h4 = *(const float4*)&hs[r][4 * in4];
            acc[r] += h4.x * w0 + h4.y * w1 + h4.z * w2 + h4.w * w3;
        }
    }
    #pragma unroll
    for (int r = 0; r < 16; r++) outp[(size_t)(row0 + r) * DIM] = acc[r];
}

// ---------------- 4) sparse masked attention ----------------
// 128 threads: tid bits [0:2)=head, [2:4)=neighbor-part, [4:7)=local row (8 rows/block)
__global__ void attn_kernel() {
    int tid = threadIdx.x;
    int head = tid & 3;
    int part = (tid >> 2) & 3;
    int rloc = tid >> 4;
    int row = blockIdx.x * 8 + rloc;
    int b_base = row & ~(Nn - 1);          // batch row base

    const float4* qp = (const float4*)(g_q + (size_t)row * DIM + head * DH);
    float4 q0 = qp[0], q1 = qp[1], q2 = qp[2], q3 = qp[3];

    float acc[16];
    #pragma unroll
    for (int t = 0; t < 16; t++) acc[t] = 0.f;
    float l = 0.f;

    int deg = g_cnt[row];
    const unsigned short* nb = g_nbr + (size_t)row * MAXD;

    for (int d = part; d < deg; d += 4) {
        int j = nb[d];
        size_t base = (size_t)(b_base + j) * DIM + head * DH;
        const float4* kp = (const float4*)(g_k + base);
        float4 k0 = kp[0], k1 = kp[1], k2 = kp[2], k3 = kp[3];
        float s = q0.x * k0.x + q0.y * k0.y + q0.z * k0.z + q0.w * k0.w
                + q1.x * k1.x + q1.y * k1.y + q1.z * k1.z + q1.w * k1.w
                + q2.x * k2.x + q2.y * k2.y + q2.z * k2.z + q2.w * k2.w
                + q3.x * k3.x + q3.y * k3.y + q3.z * k3.z + q3.w * k3.w;
        float p = __expf(s * SCALE);
        l += p;
        const float4* vp = (const float4*)(g_v + base);
        float4 v0 = vp[0], v1 = vp[1], v2 = vp[2], v3 = vp[3];
        acc[0]  += p * v0.x; acc[1]  += p * v0.y; acc[2]  += p * v0.z; acc[3]  += p * v0.w;
        acc[4]  += p * v1.x; acc[5]  += p * v1.y; acc[6]  += p * v1.z; acc[7]  += p * v1.w;
        acc[8]  += p * v2.x; acc[9]  += p * v2.y; acc[10] += p * v2.z; acc[11] += p * v2.w;
        acc[12] += p * v3.x; acc[13] += p * v3.y; acc[14] += p * v3.z; acc[15] += p * v3.w;
    }

    // reduce over the 4 neighbor-parts (lane bits 2,3)
    #pragma unroll
    for (int ofs = 4; ofs <= 8; ofs <<= 1) {
        l += __shfl_xor_sync(0xffffffffu, l, ofs);
        #pragma unroll
        for (int t = 0; t < 16; t++)
            acc[t] += __shfl_xor_sync(0xffffffffu, acc[t], ofs);
    }

    if (part == 0) {
        float inv = 1.f / l;
        float4* op = (float4*)(g_o + (size_t)row * DIM + head * DH);
        op[0] = make_float4(acc[0] * inv, acc[1] * inv, acc[2] * inv, acc[3] * inv);
        op[1] = make_float4(acc[4] * inv, acc[5] * inv, acc[6] * inv, acc[7] * inv);
        op[2] = make_float4(acc[8] * inv, acc[9] * inv, acc[10] * inv, acc[11] * inv);
        op[3] = make_float4(acc[12] * inv, acc[13] * inv, acc[14] * inv, acc[15] * inv);
    }
}

// ---------------- 5) out-proj + gate + residual ----------------
// 128 threads: 16 rows/block, 8 threads/row, each thread 8 output cols
__global__ void outgate_kernel(float* __restrict__ x,
                               const float* __restrict__ Wo,
                               const float* __restrict__ bo,
                               const float* __restrict__ Wg) {
    __shared__ float os[16][65];
    int tid = threadIdx.x;
    int row0 = blockIdx.x * 16;

    for (int i = tid; i < 16 * 16; i += 128) {
        int r = i >> 4, c4 = i & 15;
        float4 t = *(const float4*)(g_o + (size_t)(row0 + r) * DIM + c4 * 4);
        os[r][c4 * 4 + 0] = t.x; os[r][c4 * 4 + 1] = t.y;
        os[r][c4 * 4 + 2] = t.z; os[r][c4 * 4 + 3] = t.w;
    }
    __syncthreads();

    int r = tid >> 3, c = tid & 7;
    int row = row0 + r;
    int col0 = c * 8;

    float po[8];
    #pragma unroll
    for (int t = 0; t < 8; t++) po[t] = __ldg(bo + col0 + t);

    float4 xa = *(const float4*)(x + (size_t)row * DIM + col0);
    float4 xb = *(const float4*)(x + (size_t)row * DIM + col0 + 4);
    float xr[8] = {xa.x, xa.y, xa.z, xa.w, xb.x, xb.y, xb.z, xb.w};

    for (int in = 0; in < DIM; in++) {
        float ov = os[r][in];
        float4 w0 = *(const float4*)(Wo + in * DIM + col0);
        float4 w1 = *(const float4*)(Wo + in * DIM + col0 + 4);
        po[0] += ov * w0.x; po[1] += ov * w0.y; po[2] += ov * w0.z; po[3] += ov * w0.w;
        po[4] += ov * w1.x; po[5] += ov * w1.y; po[6] += ov * w1.z; po[7] += ov * w1.w;
    }

    float gp = 0.f;
    #pragma unroll
    for (int t = 0; t < 8; t++) {
        int col = col0 + t;
        gp += po[t] * __ldg(Wg + col) + xr[t] * __ldg(Wg + 64 + col)
            + (po[t] - xr[t]) * __ldg(Wg + 128 + col);
    }
    gp += __shfl_xor_sync(0xffffffffu, gp, 1);
    gp += __shfl_xor_sync(0xffffffffu, gp, 2);
    gp += __shfl_xor_sync(0xffffffffu, gp, 4);

    float gt = 1.f / (1.f + __expf(-gp));
    #pragma unroll
    for (int t = 0; t < 8; t++) xr[t] = po[t] * gt + xr[t] * (1.f - gt);

    *(float4*)(x + (size_t)row * DIM + col0)     = make_float4(xr[0], xr[1], xr[2], xr[3]);
    *(float4*)(x + (size_t)row * DIM + col0 + 4) = make_float4(xr[4], xr[5], xr[6], xr[7]);
}

// ---------------- launch ----------------
extern "C" void kernel_launch(void* const* d_in, const int* in_sizes, int n_in,
                              void* d_out, int out_size) {
    const float* nf   = (const float*)d_in[0];   // (B,N,32)
    const float* adj  = (const float*)d_in[1];   // (B,N,N)
    const float* Wfc  = (const float*)d_in[2];   // (32,64)
    const float* bfc  = (const float*)d_in[3];   // (64,)
    const float* lng  = (const float*)d_in[4];   // (3,64)
    const float* lnb  = (const float*)d_in[5];   // (3,64)
    const float* Wq   = (const float*)d_in[6];   // (3,64,64)
    const float* bq   = (const float*)d_in[7];   // (3,64)
    const float* Wkv  = (const float*)d_in[8];   // (3,64,128)
    const float* bkv  = (const float*)d_in[9];   // (3,128)
    const float* Wo   = (const float*)d_in[10];  // (3,64,64)
    const float* bo   = (const float*)d_in[11];  // (3,64)
    const float* Wg   = (const float*)d_in[12];  // (3,192,1)
    float* x = (float*)d_out;                    // (B,N,64)

    build_nbr_kernel<<<BN / 8, 256>>>(adj);
    fc_kernel<<<(BN * DIM + 255) / 256, 256>>>(nf, Wfc, bfc, x);

    for (int i = 0; i < 3; i++) {
        ln_qkv_kernel<<<BN / 16, 192>>>(x, lng + i * 64, lnb + i * 64,
                                        Wq + i * 64 * 64, bq + i * 64,
                                        Wkv + i * 64 * 128, bkv + i * 128);
        attn_kernel<<<BN / 8, 128>>>();
        outgate_kernel<<<BN / 16, 128>>>(x, Wo + i * 64 * 64, bo + i * 64,
                                         Wg + i * 192);
    }
}

// round 4
// speedup vs baseline: 1.2348x; 1.2348x over previous
#include <cuda_runtime.h>
#include <cuda_bf16.h>

#define Bb   4
#define Nn   2048
#define BN   (Bb*Nn)      // 8192
#define DIM  64
#define FIN  32
#define HEADS 4
#define DH   16
#define MAXD 384
#define SCALE 0.25f

// ---------------- device scratch (static, allocation-free) ----------------
__device__ __align__(256) float g_q[BN*DIM];
__device__ __align__(256) float g_k[BN*DIM];
__device__ __align__(256) float g_v[BN*DIM];
__device__ __align__(256) float g_o[BN*DIM];
__device__ unsigned short g_nbr[(size_t)BN*MAXD];
__device__ int g_cnt[BN];

// ---------------- 1) adjacency -> neighbor lists (once) ----------------
__global__ void build_nbr_kernel(const float* __restrict__ adj) {
    int warp = blockIdx.x * (blockDim.x >> 5) + (threadIdx.x >> 5);
    if (warp >= BN) return;
    int lane = threadIdx.x & 31;
    const float* a = adj + (size_t)warp * Nn;
    unsigned short* nb = g_nbr + (size_t)warp * MAXD;
    int cnt = 0;
    for (int j0 = 0; j0 < Nn; j0 += 32) {
        float v = a[j0 + lane];
        unsigned m = __ballot_sync(0xffffffffu, v > 0.f);
        if (v > 0.f) {
            int pos = cnt + __popc(m & ((1u << lane) - 1u));
            if (pos < MAXD) nb[pos] = (unsigned short)(j0 + lane);
        }
        cnt += __popc(m);
    }
    if (lane == 0) g_cnt[warp] = min(cnt, MAXD);
}

// ---------------- 2) fc: x = relu(nf @ W_fc + b_fc) ----------------
__global__ void fc_kernel(const float* __restrict__ nf,
                          const float* __restrict__ W,
                          const float* __restrict__ b,
                          float* __restrict__ x) {
    int idx = blockIdx.x * blockDim.x + threadIdx.x;   // BN*64
    if (idx >= BN * DIM) return;
    int row = idx >> 6, o = idx & 63;
    const float* nr = nf + (size_t)row * FIN;
    float acc = __ldg(b + o);
    #pragma unroll
    for (int i = 0; i < FIN; i++) acc += nr[i] * __ldg(W + i * DIM + o);
    x[idx] = fmaxf(acc, 0.f);
}

// ---------------- 3) LN + QKV projections (16 rows / block, 192 thr) ----------------
__global__ void ln_qkv_kernel(const float* __restrict__ x,
                              const float* __restrict__ lng,
                              const float* __restrict__ lnb,
                              const float* __restrict__ Wq,
                              const float* __restrict__ bq,
                              const float* __restrict__ Wkv,
                              const float* __restrict__ bkv) {
    __shared__ float hs[16][DIM];
    __shared__ float mu_s[16], rs_s[16];
    int tid = threadIdx.x;                 // 192
    int row0 = blockIdx.x * 16;

    const float4* xv = (const float4*)(x + (size_t)row0 * DIM);
    float4* hv = (float4*)&hs[0][0];
    for (int i = tid; i < 16 * 16; i += 192) hv[i] = xv[i];
    __syncthreads();

    if (tid < 16) {
        float m = 0.f;
        #pragma unroll
        for (int j = 0; j < DIM; j++) m += hs[tid][j];
        m *= (1.f / DIM);
        float v = 0.f;
        #pragma unroll
        for (int j = 0; j < DIM; j++) { float d = hs[tid][j] - m; v += d * d; }
        v *= (1.f / DIM);
        mu_s[tid] = m;
        rs_s[tid] = rsqrtf(v + 1e-5f);
    }
    __syncthreads();
    for (int i = tid; i < 16 * DIM; i += 192) {
        int r = i >> 6, c = i & 63;
        hs[r][c] = (hs[r][c] - mu_s[r]) * rs_s[r] * __ldg(lng + c) + __ldg(lnb + c);
    }
    __syncthreads();

    int o = tid;
    const float* wp; int ws; float bias; float* outp;
    if (o < 64)       { wp = Wq + o;          ws = 64;  bias = __ldg(bq + o);        outp = g_q + o; }
    else if (o < 128) { wp = Wkv + (o - 64);  ws = 128; bias = __ldg(bkv + (o - 64)); outp = g_k + (o - 64); }
    else              { wp = Wkv + (o - 64);  ws = 128; bias = __ldg(bkv + (o - 64)); outp = g_v + (o - 128); }

    float acc[16];
    #pragma unroll
    for (int r = 0; r < 16; r++) acc[r] = bias;

    for (int in4 = 0; in4 < 16; in4++) {
        float w0 = __ldg(wp + (4 * in4 + 0) * ws);
        float w1 = __ldg(wp + (4 * in4 + 1) * ws);
        float w2 = __ldg(wp + (4 * in4 + 2) * ws);
        float w3 = __ldg(wp + (4 * in4 + 3) * ws);
        #pragma unroll
        for (int r = 0; r < 16; r++) {
            float4 h4 = *(const float4*)&hs[r][4 * in4];
            acc[r] += h4.x * w0 + h4.y * w1 + h4.z * w2 + h4.w * w3;
        }
    }
    #pragma unroll
    for (int r = 0; r < 16; r++) outp[(size_t)(row0 + r) * DIM] = acc[r];
}

// ---------------- 4) sparse masked attention (v3: coalesced + uniform trip count) ----------------
// One warp per row. lane = part*8 + c. 8 lanes cover a K/V row (2 x 128B lines,
// one wavefront per line per LDG). Lane owns cols [4c,4c+4) (head c>>2) and
// [32+4c,32+4c+4) (head 2+(c>>2)). Dot partials reduced via shfl_xor 1,2.
// CORRECTNESS FIX vs v2: all lanes run the SAME number of loop iterations
// (dmax = ceil(deg/4)*4) so every in-loop __shfl_xor_sync is fully converged;
// tail steps are predicated (p=0) and load nb[0] (valid: self-loop => deg>=1).
__global__ void attn_kernel() {
    int lane = threadIdx.x & 31;
    int warp = threadIdx.x >> 5;
    int row = blockIdx.x * 8 + warp;
    int part = lane >> 3;          // 0..3 neighbor split
    int c = lane & 7;              // 0..7 column chunk
    int b_base = row & ~(Nn - 1);

    const float4* qp = (const float4*)(g_q + (size_t)row * DIM);
    float4 qa = qp[c];
    float4 qb = qp[8 + c];

    float a0 = 0.f, a1 = 0.f, a2 = 0.f, a3 = 0.f;   // head c>>2 accum
    float b0 = 0.f, b1 = 0.f, b2 = 0.f, b3 = 0.f;   // head (c>>2)+2 accum
    float l1 = 0.f, l2 = 0.f;

    int deg = g_cnt[row];
    int dmax = (deg + 3) & ~3;     // uniform trip count across all 4 parts
    const unsigned short* nb = g_nbr + (size_t)row * MAXD;

    for (int d = part; d < dmax; d += 4) {
        bool act = d < deg;
        int j = act ? nb[d] : nb[0];
        size_t base = (size_t)(b_base + j) * DIM;
        const float4* kp = (const float4*)(g_k + base);
        float4 ka = kp[c];
        float4 kb = kp[8 + c];
        float s1 = qa.x * ka.x + qa.y * ka.y + qa.z * ka.z + qa.w * ka.w;
        float s2 = qb.x * kb.x + qb.y * kb.y + qb.z * kb.z + qb.w * kb.w;
        s1 += __shfl_xor_sync(0xffffffffu, s1, 1);
        s2 += __shfl_xor_sync(0xffffffffu, s2, 1);
        s1 += __shfl_xor_sync(0xffffffffu, s1, 2);
        s2 += __shfl_xor_sync(0xffffffffu, s2, 2);
        float p1 = act ? __expf(s1 * SCALE) : 0.f;
        float p2 = act ? __expf(s2 * SCALE) : 0.f;
        l1 += p1;
        l2 += p2;
        const float4* vp = (const float4*)(g_v + base);
        float4 va = vp[c];
        float4 vb = vp[8 + c];
        a0 += p1 * va.x; a1 += p1 * va.y; a2 += p1 * va.z; a3 += p1 * va.w;
        b0 += p2 * vb.x; b1 += p2 * vb.y; b2 += p2 * vb.z; b3 += p2 * vb.w;
    }

    // reduce the 4 neighbor-parts (lane bits 3,4)
    #pragma unroll
    for (int ofs = 8; ofs <= 16; ofs <<= 1) {
        l1 += __shfl_xor_sync(0xffffffffu, l1, ofs);
        l2 += __shfl_xor_sync(0xffffffffu, l2, ofs);
        a0 += __shfl_xor_sync(0xffffffffu, a0, ofs);
        a1 += __shfl_xor_sync(0xffffffffu, a1, ofs);
        a2 += __shfl_xor_sync(0xffffffffu, a2, ofs);
        a3 += __shfl_xor_sync(0xffffffffu, a3, ofs);
        b0 += __shfl_xor_sync(0xffffffffu, b0, ofs);
        b1 += __shfl_xor_sync(0xffffffffu, b1, ofs);
        b2 += __shfl_xor_sync(0xffffffffu, b2, ofs);
        b3 += __shfl_xor_sync(0xffffffffu, b3, ofs);
    }

    if (part == 0) {
        float i1 = 1.f / l1;
        float i2 = 1.f / l2;
        float4* op = (float4*)(g_o + (size_t)row * DIM);
        op[c]     = make_float4(a0 * i1, a1 * i1, a2 * i1, a3 * i1);
        op[8 + c] = make_float4(b0 * i2, b1 * i2, b2 * i2, b3 * i2);
    }
}

// ---------------- 5) out-proj + gate + residual ----------------
__global__ void outgate_kernel(float* __restrict__ x,
                               const float* __restrict__ Wo,
                               const float* __restrict__ bo,
                               const float* __restrict__ Wg) {
    __shared__ float os[16][65];
    int tid = threadIdx.x;
    int row0 = blockIdx.x * 16;

    for (int i = tid; i < 16 * 16; i += 128) {
        int r = i >> 4, c4 = i & 15;
        float4 t = *(const float4*)(g_o + (size_t)(row0 + r) * DIM + c4 * 4);
        os[r][c4 * 4 + 0] = t.x; os[r][c4 * 4 + 1] = t.y;
        os[r][c4 * 4 + 2] = t.z; os[r][c4 * 4 + 3] = t.w;
    }
    __syncthreads();

    int r = tid >> 3, c = tid & 7;
    int row = row0 + r;
    int col0 = c * 8;

    float po[8];
    #pragma unroll
    for (int t = 0; t < 8; t++) po[t] = __ldg(bo + col0 + t);

    float4 xa = *(const float4*)(x + (size_t)row * DIM + col0);
    float4 xb = *(const float4*)(x + (size_t)row * DIM + col0 + 4);
    float xr[8] = {xa.x, xa.y, xa.z, xa.w, xb.x, xb.y, xb.z, xb.w};

    for (int in = 0; in < DIM; in++) {
        float ov = os[r][in];
        float4 w0 = *(const float4*)(Wo + in * DIM + col0);
        float4 w1 = *(const float4*)(Wo + in * DIM + col0 + 4);
        po[0] += ov * w0.x; po[1] += ov * w0.y; po[2] += ov * w0.z; po[3] += ov * w0.w;
        po[4] += ov * w1.x; po[5] += ov * w1.y; po[6] += ov * w1.z; po[7] += ov * w1.w;
    }

    float gp = 0.f;
    #pragma unroll
    for (int t = 0; t < 8; t++) {
        int col = col0 + t;
        gp += po[t] * __ldg(Wg + col) + xr[t] * __ldg(Wg + 64 + col)
            + (po[t] - xr[t]) * __ldg(Wg + 128 + col);
    }
    gp += __shfl_xor_sync(0xffffffffu, gp, 1);
    gp += __shfl_xor_sync(0xffffffffu, gp, 2);
    gp += __shfl_xor_sync(0xffffffffu, gp, 4);

    float gt = 1.f / (1.f + __expf(-gp));
    #pragma unroll
    for (int t = 0; t < 8; t++) xr[t] = po[t] * gt + xr[t] * (1.f - gt);

    *(float4*)(x + (size_t)row * DIM + col0)     = make_float4(xr[0], xr[1], xr[2], xr[3]);
    *(float4*)(x + (size_t)row * DIM + col0 + 4) = make_float4(xr[4], xr[5], xr[6], xr[7]);
}

// ---------------- launch ----------------
extern "C" void kernel_launch(void* const* d_in, const int* in_sizes, int n_in,
                              void* d_out, int out_size) {
    const float* nf   = (const float*)d_in[0];
    const float* adj  = (const float*)d_in[1];
    const float* Wfc  = (const float*)d_in[2];
    const float* bfc  = (const float*)d_in[3];
    const float* lng  = (const float*)d_in[4];
    const float* lnb  = (const float*)d_in[5];
    const float* Wq   = (const float*)d_in[6];
    const float* bq   = (const float*)d_in[7];
    const float* Wkv  = (const float*)d_in[8];
    const float* bkv  = (const float*)d_in[9];
    const float* Wo   = (const float*)d_in[10];
    const float* bo   = (const float*)d_in[11];
    const float* Wg   = (const float*)d_in[12];
    float* x = (float*)d_out;

    build_nbr_kernel<<<BN / 8, 256>>>(adj);
    fc_kernel<<<(BN * DIM + 255) / 256, 256>>>(nf, Wfc, bfc, x);

    for (int i = 0; i < 3; i++) {
        ln_qkv_kernel<<<BN / 16, 192>>>(x, lng + i * 64, lnb + i * 64,
                                        Wq + i * 64 * 64, bq + i * 64,
                                        Wkv + i * 64 * 128, bkv + i * 128);
        attn_kernel<<<BN / 8, 256>>>();
        outgate_kernel<<<BN / 16, 128>>>(x, Wo + i * 64 * 64, bo + i * 64,
                                         Wg + i * 192);
    }
}

// round 5
// speedup vs baseline: 1.2698x; 1.0284x over previous
#include <cuda_runtime.h>
#include <cuda_bf16.h>

#define Bb   4
#define Nn   2048
#define BN   (Bb*Nn)      // 8192
#define DIM  64
#define FIN  32
#define HEADS 4
#define DH   16
#define MAXD 384
#define SCALE 0.25f

// ---------------- device scratch (static, allocation-free) ----------------
__device__ __align__(256) float g_q[BN*DIM];
__device__ __align__(256) float g_k[BN*DIM];
__device__ __align__(256) float g_v[BN*DIM];
__device__ __align__(256) float g_o[BN*DIM];
__device__ unsigned short g_nbr[(size_t)BN*MAXD];
__device__ int g_cnt[BN];

// ---------------- 1) adjacency -> neighbor lists (float4, 128 cols/iter) ----------------
__global__ void build_nbr_kernel(const float* __restrict__ adj) {
    int warp = blockIdx.x * (blockDim.x >> 5) + (threadIdx.x >> 5);
    if (warp >= BN) return;
    int lane = threadIdx.x & 31;
    const float4* a4 = (const float4*)(adj + (size_t)warp * Nn);
    unsigned short* nb = g_nbr + (size_t)warp * MAXD;
    unsigned lmask = (1u << lane) - 1u;
    int cnt = 0;
    for (int j0 = 0; j0 < Nn; j0 += 128) {
        float4 v = a4[(j0 >> 2) + lane];
        int jbase = j0 + 4 * lane;
        #pragma unroll
        for (int comp = 0; comp < 4; comp++) {
            float val = (comp == 0) ? v.x : (comp == 1) ? v.y : (comp == 2) ? v.z : v.w;
            unsigned m = __ballot_sync(0xffffffffu, val > 0.f);
            if (val > 0.f) {
                int pos = cnt + __popc(m & lmask);
                if (pos < MAXD) nb[pos] = (unsigned short)(jbase + comp);
            }
            cnt += __popc(m);
        }
    }
    if (lane == 0) g_cnt[warp] = min(cnt, MAXD);
}

// ---------------- 2) fc: x = relu(nf @ W_fc + b_fc) ----------------
__global__ void fc_kernel(const float* __restrict__ nf,
                          const float* __restrict__ W,
                          const float* __restrict__ b,
                          float* __restrict__ x) {
    int idx = blockIdx.x * blockDim.x + threadIdx.x;   // BN*64
    if (idx >= BN * DIM) return;
    int row = idx >> 6, o = idx & 63;
    const float* nr = nf + (size_t)row * FIN;
    float acc = __ldg(b + o);
    #pragma unroll
    for (int i = 0; i < FIN; i++) acc += nr[i] * __ldg(W + i * DIM + o);
    x[idx] = fmaxf(acc, 0.f);
}

// ---------------- 3) LN + QKV projections (16 rows / block, 192 thr) ----------------
__global__ void ln_qkv_kernel(const float* __restrict__ x,
                              const float* __restrict__ lng,
                              const float* __restrict__ lnb,
                              const float* __restrict__ Wq,
                              const float* __restrict__ bq,
                              const float* __restrict__ Wkv,
                              const float* __restrict__ bkv) {
    __shared__ float hs[16][DIM];
    __shared__ float mu_s[16], rs_s[16];
    int tid = threadIdx.x;                 // 192
    int row0 = blockIdx.x * 16;

    const float4* xv = (const float4*)(x + (size_t)row0 * DIM);
    float4* hv = (float4*)&hs[0][0];
    for (int i = tid; i < 16 * 16; i += 192) hv[i] = xv[i];
    __syncthreads();

    if (tid < 16) {
        float m = 0.f;
        #pragma unroll
        for (int j = 0; j < DIM; j++) m += hs[tid][j];
        m *= (1.f / DIM);
        float v = 0.f;
        #pragma unroll
        for (int j = 0; j < DIM; j++) { float d = hs[tid][j] - m; v += d * d; }
        v *= (1.f / DIM);
        mu_s[tid] = m;
        rs_s[tid] = rsqrtf(v + 1e-5f);
    }
    __syncthreads();
    for (int i = tid; i < 16 * DIM; i += 192) {
        int r = i >> 6, c = i & 63;
        hs[r][c] = (hs[r][c] - mu_s[r]) * rs_s[r] * __ldg(lng + c) + __ldg(lnb + c);
    }
    __syncthreads();

    int o = tid;
    const float* wp; int ws; float bias; float* outp;
    if (o < 64)       { wp = Wq + o;          ws = 64;  bias = __ldg(bq + o);        outp = g_q + o; }
    else if (o < 128) { wp = Wkv + (o - 64);  ws = 128; bias = __ldg(bkv + (o - 64)); outp = g_k + (o - 64); }
    else              { wp = Wkv + (o - 64);  ws = 128; bias = __ldg(bkv + (o - 64)); outp = g_v + (o - 128); }

    float acc[16];
    #pragma unroll
    for (int r = 0; r < 16; r++) acc[r] = bias;

    for (int in4 = 0; in4 < 16; in4++) {
        float w0 = __ldg(wp + (4 * in4 + 0) * ws);
        float w1 = __ldg(wp + (4 * in4 + 1) * ws);
        float w2 = __ldg(wp + (4 * in4 + 2) * ws);
        float w3 = __ldg(wp + (4 * in4 + 3) * ws);
        #pragma unroll
        for (int r = 0; r < 16; r++) {
            float4 h4 = *(const float4*)&hs[r][4 * in4];
            acc[r] += h4.x * w0 + h4.y * w1 + h4.z * w2 + h4.w * w3;
        }
    }
    #pragma unroll
    for (int r = 0; r < 16; r++) outp[(size_t)(row0 + r) * DIM] = acc[r];
}

// ---------------- 4) sparse masked attention (v4: 2-neighbor ILP) ----------------
// One warp per row. lane = part*8 + c. 8 lanes cover a K/V row (one wavefront
// per 128B line). Two neighbors (A at d, B at d+4) processed per iteration with
// fully interleaved load/dot/shuffle pipelines. Uniform trip count (dmax
// rounded to 8) keeps all shuffles converged; tail steps predicated to p=0.
__global__ void attn_kernel() {
    int lane = threadIdx.x & 31;
    int warp = threadIdx.x >> 5;
    int row = blockIdx.x * 8 + warp;
    int part = lane >> 3;          // 0..3 neighbor split
    int c = lane & 7;              // 0..7 column chunk
    int b_base = row & ~(Nn - 1);

    const float4* qp = (const float4*)(g_q + (size_t)row * DIM);
    float4 qa = qp[c];
    float4 qb = qp[8 + c];

    float a0 = 0.f, a1 = 0.f, a2 = 0.f, a3 = 0.f;   // head c>>2 accum
    float b0 = 0.f, b1 = 0.f, b2 = 0.f, b3 = 0.f;   // head (c>>2)+2 accum
    float l1 = 0.f, l2 = 0.f;

    int deg = g_cnt[row];
    int dmax = (deg + 7) & ~7;     // uniform trip count, unroll-2
    const unsigned short* nb = g_nbr + (size_t)row * MAXD;

    for (int d = part; d < dmax; d += 8) {
        bool actA = d < deg;
        bool actB = d + 4 < deg;
        int jA = actA ? nb[d] : nb[0];
        int jB = actB ? nb[d + 4] : nb[0];
        size_t baseA = (size_t)(b_base + jA) * DIM;
        size_t baseB = (size_t)(b_base + jB) * DIM;

        const float4* kpA = (const float4*)(g_k + baseA);
        const float4* kpB = (const float4*)(g_k + baseB);
        float4 kaA = kpA[c];
        float4 kaB = kpB[c];
        float4 kbA = kpA[8 + c];
        float4 kbB = kpB[8 + c];
        const float4* vpA = (const float4*)(g_v + baseA);
        const float4* vpB = (const float4*)(g_v + baseB);
        float4 vaA = vpA[c];
        float4 vaB = vpB[c];
        float4 vbA = vpA[8 + c];
        float4 vbB = vpB[8 + c];

        float s1A = qa.x * kaA.x + qa.y * kaA.y + qa.z * kaA.z + qa.w * kaA.w;
        float s1B = qa.x * kaB.x + qa.y * kaB.y + qa.z * kaB.z + qa.w * kaB.w;
        float s2A = qb.x * kbA.x + qb.y * kbA.y + qb.z * kbA.z + qb.w * kbA.w;
        float s2B = qb.x * kbB.x + qb.y * kbB.y + qb.z * kbB.z + qb.w * kbB.w;

        s1A += __shfl_xor_sync(0xffffffffu, s1A, 1);
        s1B += __shfl_xor_sync(0xffffffffu, s1B, 1);
        s2A += __shfl_xor_sync(0xffffffffu, s2A, 1);
        s2B += __shfl_xor_sync(0xffffffffu, s2B, 1);
        s1A += __shfl_xor_sync(0xffffffffu, s1A, 2);
        s1B += __shfl_xor_sync(0xffffffffu, s1B, 2);
        s2A += __shfl_xor_sync(0xffffffffu, s2A, 2);
        s2B += __shfl_xor_sync(0xffffffffu, s2B, 2);

        float p1A = actA ? __expf(s1A * SCALE) : 0.f;
        float p1B = actB ? __expf(s1B * SCALE) : 0.f;
        float p2A = actA ? __expf(s2A * SCALE) : 0.f;
        float p2B = actB ? __expf(s2B * SCALE) : 0.f;
        l1 += p1A + p1B;
        l2 += p2A + p2B;

        a0 += p1A * vaA.x + p1B * vaB.x;
        a1 += p1A * vaA.y + p1B * vaB.y;
        a2 += p1A * vaA.z + p1B * vaB.z;
        a3 += p1A * vaA.w + p1B * vaB.w;
        b0 += p2A * vbA.x + p2B * vbB.x;
        b1 += p2A * vbA.y + p2B * vbB.y;
        b2 += p2A * vbA.z + p2B * vbB.z;
        b3 += p2A * vbA.w + p2B * vbB.w;
    }

    // reduce the 4 neighbor-parts (lane bits 3,4)
    #pragma unroll
    for (int ofs = 8; ofs <= 16; ofs <<= 1) {
        l1 += __shfl_xor_sync(0xffffffffu, l1, ofs);
        l2 += __shfl_xor_sync(0xffffffffu, l2, ofs);
        a0 += __shfl_xor_sync(0xffffffffu, a0, ofs);
        a1 += __shfl_xor_sync(0xffffffffu, a1, ofs);
        a2 += __shfl_xor_sync(0xffffffffu, a2, ofs);
        a3 += __shfl_xor_sync(0xffffffffu, a3, ofs);
        b0 += __shfl_xor_sync(0xffffffffu, b0, ofs);
        b1 += __shfl_xor_sync(0xffffffffu, b1, ofs);
        b2 += __shfl_xor_sync(0xffffffffu, b2, ofs);
        b3 += __shfl_xor_sync(0xffffffffu, b3, ofs);
    }

    if (part == 0) {
        float i1 = 1.f / l1;
        float i2 = 1.f / l2;
        float4* op = (float4*)(g_o + (size_t)row * DIM);
        op[c]     = make_float4(a0 * i1, a1 * i1, a2 * i1, a3 * i1);
        op[8 + c] = make_float4(b0 * i2, b1 * i2, b2 * i2, b3 * i2);
    }
}

// ---------------- 5) out-proj + gate + residual ----------------
__global__ void outgate_kernel(float* __restrict__ x,
                               const float* __restrict__ Wo,
                               const float* __restrict__ bo,
                               const float* __restrict__ Wg) {
    __shared__ float os[16][65];
    int tid = threadIdx.x;
    int row0 = blockIdx.x * 16;

    for (int i = tid; i < 16 * 16; i += 128) {
        int r = i >> 4, c4 = i & 15;
        float4 t = *(const float4*)(g_o + (size_t)(row0 + r) * DIM + c4 * 4);
        os[r][c4 * 4 + 0] = t.x; os[r][c4 * 4 + 1] = t.y;
        os[r][c4 * 4 + 2] = t.z; os[r][c4 * 4 + 3] = t.w;
    }
    __syncthreads();

    int r = tid >> 3, c = tid & 7;
    int row = row0 + r;
    int col0 = c * 8;

    float po[8];
    #pragma unroll
    for (int t = 0; t < 8; t++) po[t] = __ldg(bo + col0 + t);

    float4 xa = *(const float4*)(x + (size_t)row * DIM + col0);
    float4 xb = *(const float4*)(x + (size_t)row * DIM + col0 + 4);
    float xr[8] = {xa.x, xa.y, xa.z, xa.w, xb.x, xb.y, xb.z, xb.w};

    for (int in = 0; in < DIM; in++) {
        float ov = os[r][in];
        float4 w0 = *(const float4*)(Wo + in * DIM + col0);
        float4 w1 = *(const float4*)(Wo + in * DIM + col0 + 4);
        po[0] += ov * w0.x; po[1] += ov * w0.y; po[2] += ov * w0.z; po[3] += ov * w0.w;
        po[4] += ov * w1.x; po[5] += ov * w1.y; po[6] += ov * w1.z; po[7] += ov * w1.w;
    }

    float gp = 0.f;
    #pragma unroll
    for (int t = 0; t < 8; t++) {
        int col = col0 + t;
        gp += po[t] * __ldg(Wg + col) + xr[t] * __ldg(Wg + 64 + col)
            + (po[t] - xr[t]) * __ldg(Wg + 128 + col);
    }
    gp += __shfl_xor_sync(0xffffffffu, gp, 1);
    gp += __shfl_xor_sync(0xffffffffu, gp, 2);
    gp += __shfl_xor_sync(0xffffffffu, gp, 4);

    float gt = 1.f / (1.f + __expf(-gp));
    #pragma unroll
    for (int t = 0; t < 8; t++) xr[t] = po[t] * gt + xr[t] * (1.f - gt);

    *(float4*)(x + (size_t)row * DIM + col0)     = make_float4(xr[0], xr[1], xr[2], xr[3]);
    *(float4*)(x + (size_t)row * DIM + col0 + 4) = make_float4(xr[4], xr[5], xr[6], xr[7]);
}

// ---------------- launch ----------------
extern "C" void kernel_launch(void* const* d_in, const int* in_sizes, int n_in,
                              void* d_out, int out_size) {
    const float* nf   = (const float*)d_in[0];
    const float* adj  = (const float*)d_in[1];
    const float* Wfc  = (const float*)d_in[2];
    const float* bfc  = (const float*)d_in[3];
    const float* lng  = (const float*)d_in[4];
    const float* lnb  = (const float*)d_in[5];
    const float* Wq   = (const float*)d_in[6];
    const float* bq   = (const float*)d_in[7];
    const float* Wkv  = (const float*)d_in[8];
    const float* bkv  = (const float*)d_in[9];
    const float* Wo   = (const float*)d_in[10];
    const float* bo   = (const float*)d_in[11];
    const float* Wg   = (const float*)d_in[12];
    float* x = (float*)d_out;

    build_nbr_kernel<<<BN / 8, 256>>>(adj);
    fc_kernel<<<(BN * DIM + 255) / 256, 256>>>(nf, Wfc, bfc, x);

    for (int i = 0; i < 3; i++) {
        ln_qkv_kernel<<<BN / 16, 192>>>(x, lng + i * 64, lnb + i * 64,
                                        Wq + i * 64 * 64, bq + i * 64,
                                        Wkv + i * 64 * 128, bkv + i * 128);
        attn_kernel<<<BN / 8, 256>>>();
        outgate_kernel<<<BN / 16, 128>>>(x, Wo + i * 64 * 64, bo + i * 64,
                                         Wg + i * 192);
    }
}

// round 6
// speedup vs baseline: 1.4178x; 1.1166x over previous
#include <cuda_runtime.h>
#include <cuda_bf16.h>

#define Bb   4
#define Nn   2048
#define BN   (Bb*Nn)      // 8192
#define DIM  64
#define FIN  32
#define HEADS 4
#define DH   16
#define MAXD 384
#define SCALE 0.25f

// ---------------- device scratch (static, allocation-free) ----------------
__device__ __align__(256) float g_q[BN*DIM];
__device__ __align__(256) float g_k[BN*DIM];
__device__ __align__(256) float g_v[BN*DIM];
__device__ __align__(256) float g_o[BN*DIM];
__device__ unsigned short g_nbr[(size_t)BN*MAXD];
__device__ int g_cnt[BN];

// ---------------- 1) adjacency -> neighbor lists (float4, 128 cols/iter) ----------------
__global__ void build_nbr_kernel(const float* __restrict__ adj) {
    int warp = blockIdx.x * (blockDim.x >> 5) + (threadIdx.x >> 5);
    if (warp >= BN) return;
    int lane = threadIdx.x & 31;
    const float4* a4 = (const float4*)(adj + (size_t)warp * Nn);
    unsigned short* nb = g_nbr + (size_t)warp * MAXD;
    unsigned lmask = (1u << lane) - 1u;
    int cnt = 0;
    for (int j0 = 0; j0 < Nn; j0 += 128) {
        float4 v = a4[(j0 >> 2) + lane];
        int jbase = j0 + 4 * lane;
        #pragma unroll
        for (int comp = 0; comp < 4; comp++) {
            float val = (comp == 0) ? v.x : (comp == 1) ? v.y : (comp == 2) ? v.z : v.w;
            unsigned m = __ballot_sync(0xffffffffu, val > 0.f);
            if (val > 0.f) {
                int pos = cnt + __popc(m & lmask);
                if (pos < MAXD) nb[pos] = (unsigned short)(jbase + comp);
            }
            cnt += __popc(m);
        }
    }
    if (lane == 0) g_cnt[warp] = min(cnt, MAXD);
}

// ---------------- shared device helper: LN + QKV from smem h ----------------
// hs[16][64] holds the pre-LN rows; 192 threads; writes g_q/g_k/g_v.
__device__ __forceinline__ void ln_qkv_body(float (*hs)[DIM], float* mu_s, float* rs_s,
                                            int tid, int row0,
                                            const float* __restrict__ lng,
                                            const float* __restrict__ lnb,
                                            const float* __restrict__ Wq,
                                            const float* __restrict__ bq,
                                            const float* __restrict__ Wkv,
                                            const float* __restrict__ bkv) {
    if (tid < 16) {
        float m = 0.f;
        #pragma unroll
        for (int j = 0; j < DIM; j++) m += hs[tid][j];
        m *= (1.f / DIM);
        float v = 0.f;
        #pragma unroll
        for (int j = 0; j < DIM; j++) { float d = hs[tid][j] - m; v += d * d; }
        v *= (1.f / DIM);
        mu_s[tid] = m;
        rs_s[tid] = rsqrtf(v + 1e-5f);
    }
    __syncthreads();
    for (int i = tid; i < 16 * DIM; i += 192) {
        int r = i >> 6, c = i & 63;
        hs[r][c] = (hs[r][c] - mu_s[r]) * rs_s[r] * __ldg(lng + c) + __ldg(lnb + c);
    }
    __syncthreads();

    int o = tid;
    const float* wp; int ws; float bias; float* outp;
    if (o < 64)       { wp = Wq + o;          ws = 64;  bias = __ldg(bq + o);        outp = g_q + o; }
    else if (o < 128) { wp = Wkv + (o - 64);  ws = 128; bias = __ldg(bkv + (o - 64)); outp = g_k + (o - 64); }
    else              { wp = Wkv + (o - 64);  ws = 128; bias = __ldg(bkv + (o - 64)); outp = g_v + (o - 128); }

    float acc[16];
    #pragma unroll
    for (int r = 0; r < 16; r++) acc[r] = bias;

    for (int in4 = 0; in4 < 16; in4++) {
        float w0 = __ldg(wp + (4 * in4 + 0) * ws);
        float w1 = __ldg(wp + (4 * in4 + 1) * ws);
        float w2 = __ldg(wp + (4 * in4 + 2) * ws);
        float w3 = __ldg(wp + (4 * in4 + 3) * ws);
        #pragma unroll
        for (int r = 0; r < 16; r++) {
            float4 h4 = *(const float4*)&hs[r][4 * in4];
            acc[r] += h4.x * w0 + h4.y * w1 + h4.z * w2 + h4.w * w3;
        }
    }
    #pragma unroll
    for (int r = 0; r < 16; r++) outp[(size_t)(row0 + r) * DIM] = acc[r];
}

// ---------------- 2) fused fc(+ReLU) + LN + QKV (layer 0 front-end) ----------------
__global__ void fc_ln_qkv_kernel(const float* __restrict__ nf,
                                 const float* __restrict__ Wfc,
                                 const float* __restrict__ bfc,
                                 float* __restrict__ x,
                                 const float* __restrict__ lng,
                                 const float* __restrict__ lnb,
                                 const float* __restrict__ Wq,
                                 const float* __restrict__ bq,
                                 const float* __restrict__ Wkv,
                                 const float* __restrict__ bkv) {
    __shared__ float hs[16][DIM];
    __shared__ float nfs[16][FIN];
    __shared__ float mu_s[16], rs_s[16];
    int tid = threadIdx.x;                 // 192
    int row0 = blockIdx.x * 16;

    const float4* nv = (const float4*)(nf + (size_t)row0 * FIN);
    float4* nsv = (float4*)&nfs[0][0];
    for (int i = tid; i < 128; i += 192) nsv[i] = nv[i];
    __syncthreads();

    for (int i = tid; i < 16 * DIM; i += 192) {
        int r = i >> 6, c = i & 63;
        float acc = __ldg(bfc + c);
        #pragma unroll
        for (int k2 = 0; k2 < FIN; k2++) acc += nfs[r][k2] * __ldg(Wfc + k2 * DIM + c);
        acc = fmaxf(acc, 0.f);
        hs[r][c] = acc;
        x[(size_t)(row0 + r) * DIM + c] = acc;
    }
    __syncthreads();

    ln_qkv_body(hs, mu_s, rs_s, tid, row0, lng, lnb, Wq, bq, Wkv, bkv);
}

// ---------------- 3) sparse masked attention (v5: lane-specialized exp) ----------------
// One warp per row. lane = part*8 + c. 8 lanes cover a K/V row (one wavefront
// per 128B line). Lane owns cols [4c,4c+4) (head c>>2) and [32+4c,..) (head
// 2+(c>>2)). Reduction trick: odd lanes swap s1/s2 so after shfl 1 + shfl 2
// even lanes hold full s1, odd lanes full s2 -> ONE exp per lane, then one
// shuffle broadcasts p back. Uniform trip count keeps shuffles converged.
__global__ void attn_kernel() {
    int lane = threadIdx.x & 31;
    int warp = threadIdx.x >> 5;
    int row = blockIdx.x * 8 + warp;
    int part = lane >> 3;          // 0..3 neighbor split
    int c = lane & 7;              // 0..7 column chunk
    bool codd = (c & 1);
    int b_base = row & ~(Nn - 1);

    const float4* qp = (const float4*)(g_q + (size_t)row * DIM);
    float4 qa = qp[c];
    float4 qb = qp[8 + c];

    float a0 = 0.f, a1 = 0.f, a2 = 0.f, a3 = 0.f;   // head c>>2 accum
    float b0 = 0.f, b1 = 0.f, b2 = 0.f, b3 = 0.f;   // head (c>>2)+2 accum
    float l1 = 0.f, l2 = 0.f;

    int deg = g_cnt[row];
    int dmax = (deg + 7) & ~7;     // uniform trip count, unroll-2
    const unsigned short* nb = g_nbr + (size_t)row * MAXD;

    for (int d = part; d < dmax; d += 8) {
        bool actA = d < deg;
        bool actB = d + 4 < deg;
        int jA = actA ? nb[d] : nb[0];
        int jB = actB ? nb[d + 4] : nb[0];
        size_t baseA = (size_t)(b_base + jA) * DIM;
        size_t baseB = (size_t)(b_base + jB) * DIM;

        const float4* kpA = (const float4*)(g_k + baseA);
        const float4* kpB = (const float4*)(g_k + baseB);
        float4 kaA = kpA[c];
        float4 kaB = kpB[c];
        float4 kbA = kpA[8 + c];
        float4 kbB = kpB[8 + c];
        const float4* vpA = (const float4*)(g_v + baseA);
        const float4* vpB = (const float4*)(g_v + baseB);
        float4 vaA = vpA[c];
        float4 vaB = vpB[c];
        float4 vbA = vpA[8 + c];
        float4 vbB = vpB[8 + c];

        float s1A = qa.x * kaA.x + qa.y * kaA.y + qa.z * kaA.z + qa.w * kaA.w;
        float s1B = qa.x * kaB.x + qa.y * kaB.y + qa.z * kaB.z + qa.w * kaB.w;
        float s2A = qb.x * kbA.x + qb.y * kbA.y + qb.z * kbA.z + qb.w * kbA.w;
        float s2B = qb.x * kbB.x + qb.y * kbB.y + qb.z * kbB.z + qb.w * kbB.w;

        // lane-specialized reduce: even c -> full s1, odd c -> full s2
        float tA = codd ? s2A : s1A;
        float oA = codd ? s1A : s2A;
        float tB = codd ? s2B : s1B;
        float oB = codd ? s1B : s2B;
        tA += __shfl_xor_sync(0xffffffffu, oA, 1);
        tB += __shfl_xor_sync(0xffffffffu, oB, 1);
        tA += __shfl_xor_sync(0xffffffffu, tA, 2);
        tB += __shfl_xor_sync(0xffffffffu, tB, 2);

        float pA = actA ? __expf(tA * SCALE) : 0.f;
        float pB = actB ? __expf(tB * SCALE) : 0.f;
        float pswA = __shfl_xor_sync(0xffffffffu, pA, 1);
        float pswB = __shfl_xor_sync(0xffffffffu, pB, 1);
        float p1A = codd ? pswA : pA;
        float p2A = codd ? pA : pswA;
        float p1B = codd ? pswB : pB;
        float p2B = codd ? pB : pswB;

        l1 += p1A + p1B;
        l2 += p2A + p2B;

        a0 += p1A * vaA.x + p1B * vaB.x;
        a1 += p1A * vaA.y + p1B * vaB.y;
        a2 += p1A * vaA.z + p1B * vaB.z;
        a3 += p1A * vaA.w + p1B * vaB.w;
        b0 += p2A * vbA.x + p2B * vbB.x;
        b1 += p2A * vbA.y + p2B * vbB.y;
        b2 += p2A * vbA.z + p2B * vbB.z;
        b3 += p2A * vbA.w + p2B * vbB.w;
    }

    // reduce the 4 neighbor-parts (lane bits 3,4)
    #pragma unroll
    for (int ofs = 8; ofs <= 16; ofs <<= 1) {
        l1 += __shfl_xor_sync(0xffffffffu, l1, ofs);
        l2 += __shfl_xor_sync(0xffffffffu, l2, ofs);
        a0 += __shfl_xor_sync(0xffffffffu, a0, ofs);
        a1 += __shfl_xor_sync(0xffffffffu, a1, ofs);
        a2 += __shfl_xor_sync(0xffffffffu, a2, ofs);
        a3 += __shfl_xor_sync(0xffffffffu, a3, ofs);
        b0 += __shfl_xor_sync(0xffffffffu, b0, ofs);
        b1 += __shfl_xor_sync(0xffffffffu, b1, ofs);
        b2 += __shfl_xor_sync(0xffffffffu, b2, ofs);
        b3 += __shfl_xor_sync(0xffffffffu, b3, ofs);
    }

    if (part == 0) {
        float i1 = 1.f / l1;
        float i2 = 1.f / l2;
        float4* op = (float4*)(g_o + (size_t)row * DIM);
        op[c]     = make_float4(a0 * i1, a1 * i1, a2 * i1, a3 * i1);
        op[8 + c] = make_float4(b0 * i2, b1 * i2, b2 * i2, b3 * i2);
    }
}

// ---------------- 4) out-proj + gate + residual body (threads 0..127) ----------------
__device__ __forceinline__ void outgate_body(float (*os)[65], float* __restrict__ x,
                                             int tid, int row0,
                                             const float* __restrict__ Wo,
                                             const float* __restrict__ bo,
                                             const float* __restrict__ Wg,
                                             float* xr_out /* 8 floats, may be null semantics via hs */,
                                             float (*hs)[DIM] /* nullable */) {
    int r = tid >> 3, c = tid & 7;
    int row = row0 + r;
    int col0 = c * 8;

    float po[8];
    #pragma unroll
    for (int t = 0; t < 8; t++) po[t] = __ldg(bo + col0 + t);

    float4 xa = *(const float4*)(x + (size_t)row * DIM + col0);
    float4 xb = *(const float4*)(x + (size_t)row * DIM + col0 + 4);
    float xr[8] = {xa.x, xa.y, xa.z, xa.w, xb.x, xb.y, xb.z, xb.w};

    for (int in = 0; in < DIM; in++) {
        float ov = os[r][in];
        float4 w0 = *(const float4*)(Wo + in * DIM + col0);
        float4 w1 = *(const float4*)(Wo + in * DIM + col0 + 4);
        po[0] += ov * w0.x; po[1] += ov * w0.y; po[2] += ov * w0.z; po[3] += ov * w0.w;
        po[4] += ov * w1.x; po[5] += ov * w1.y; po[6] += ov * w1.z; po[7] += ov * w1.w;
    }

    float gp = 0.f;
    #pragma unroll
    for (int t = 0; t < 8; t++) {
        int col = col0 + t;
        gp += po[t] * __ldg(Wg + col) + xr[t] * __ldg(Wg + 64 + col)
            + (po[t] - xr[t]) * __ldg(Wg + 128 + col);
    }
    gp += __shfl_xor_sync(0xffffffffu, gp, 1);
    gp += __shfl_xor_sync(0xffffffffu, gp, 2);
    gp += __shfl_xor_sync(0xffffffffu, gp, 4);

    float gt = 1.f / (1.f + __expf(-gp));
    #pragma unroll
    for (int t = 0; t < 8; t++) xr[t] = po[t] * gt + xr[t] * (1.f - gt);

    *(float4*)(x + (size_t)row * DIM + col0)     = make_float4(xr[0], xr[1], xr[2], xr[3]);
    *(float4*)(x + (size_t)row * DIM + col0 + 4) = make_float4(xr[4], xr[5], xr[6], xr[7]);
    if (hs) {
        #pragma unroll
        for (int t = 0; t < 8; t++) hs[r][col0 + t] = xr[t];
    }
}

// ---------------- 5a) fused outgate + LN + QKV (layers 0,1 -> feed 1,2) ----------------
__global__ void outgate_ln_qkv_kernel(float* __restrict__ x,
                                      const float* __restrict__ Wo,
                                      const float* __restrict__ bo,
                                      const float* __restrict__ Wg,
                                      const float* __restrict__ lng,
                                      const float* __restrict__ lnb,
                                      const float* __restrict__ Wq,
                                      const float* __restrict__ bq,
                                      const float* __restrict__ Wkv,
                                      const float* __restrict__ bkv) {
    __shared__ float os[16][65];
    __shared__ float hs[16][DIM];
    __shared__ float mu_s[16], rs_s[16];
    int tid = threadIdx.x;         // 192
    int row0 = blockIdx.x * 16;

    for (int i = tid; i < 16 * 16; i += 192) {
        int r = i >> 4, c4 = i & 15;
        float4 t = *(const float4*)(g_o + (size_t)(row0 + r) * DIM + c4 * 4);
        os[r][c4 * 4 + 0] = t.x; os[r][c4 * 4 + 1] = t.y;
        os[r][c4 * 4 + 2] = t.z; os[r][c4 * 4 + 3] = t.w;
    }
    __syncthreads();

    if (tid < 128) outgate_body(os, x, tid, row0, Wo, bo, Wg, 0, hs);
    __syncthreads();

    ln_qkv_body(hs, mu_s, rs_s, tid, row0, lng, lnb, Wq, bq, Wkv, bkv);
}

// ---------------- 5b) final outgate (layer 2) ----------------
__global__ void outgate_kernel(float* __restrict__ x,
                               const float* __restrict__ Wo,
                               const float* __restrict__ bo,
                               const float* __restrict__ Wg) {
    __shared__ float os[16][65];
    int tid = threadIdx.x;         // 128
    int row0 = blockIdx.x * 16;

    for (int i = tid; i < 16 * 16; i += 128) {
        int r = i >> 4, c4 = i & 15;
        float4 t = *(const float4*)(g_o + (size_t)(row0 + r) * DIM + c4 * 4);
        os[r][c4 * 4 + 0] = t.x; os[r][c4 * 4 + 1] = t.y;
        os[r][c4 * 4 + 2] = t.z; os[r][c4 * 4 + 3] = t.w;
    }
    __syncthreads();

    outgate_body(os, x, tid, row0, Wo, bo, Wg, 0, 0);
}

// ---------------- launch ----------------
extern "C" void kernel_launch(void* const* d_in, const int* in_sizes, int n_in,
                              void* d_out, int out_size) {
    const float* nf   = (const float*)d_in[0];
    const float* adj  = (const float*)d_in[1];
    const float* Wfc  = (const float*)d_in[2];
    const float* bfc  = (const float*)d_in[3];
    const float* lng  = (const float*)d_in[4];
    const float* lnb  = (const float*)d_in[5];
    const float* Wq   = (const float*)d_in[6];
    const float* bq   = (const float*)d_in[7];
    const float* Wkv  = (const float*)d_in[8];
    const float* bkv  = (const float*)d_in[9];
    const float* Wo   = (const float*)d_in[10];
    const float* bo   = (const float*)d_in[11];
    const float* Wg   = (const float*)d_in[12];
    float* x = (float*)d_out;

    build_nbr_kernel<<<BN / 8, 256>>>(adj);
    fc_ln_qkv_kernel<<<BN / 16, 192>>>(nf, Wfc, bfc, x,
                                       lng, lnb, Wq, bq, Wkv, bkv);
    attn_kernel<<<BN / 8, 256>>>();
    for (int i = 0; i < 2; i++) {
        outgate_ln_qkv_kernel<<<BN / 16, 192>>>(x,
                                                Wo + i * 64 * 64, bo + i * 64, Wg + i * 192,
                                                lng + (i + 1) * 64, lnb + (i + 1) * 64,
                                                Wq + (i + 1) * 64 * 64, bq + (i + 1) * 64,
                                                Wkv + (i + 1) * 64 * 128, bkv + (i + 1) * 128);
        attn_kernel<<<BN / 8, 256>>>();
    }
    outgate_kernel<<<BN / 16, 128>>>(x, Wo + 2 * 64 * 64, bo + 2 * 64, Wg + 2 * 192);
}

// round 7
// speedup vs baseline: 1.8336x; 1.2933x over previous
#include <cuda_runtime.h>
#include <cuda_fp16.h>

#define Bb   4
#define Nn   2048
#define BN   (Bb*Nn)      // 8192
#define DIM  64
#define FIN  32
#define MAXD 384
#define SCALE 0.25f

// ---------------- device scratch (static, allocation-free) ----------------
__device__ __align__(256) float  g_q[BN*DIM];
__device__ __align__(256) __half g_kh[BN*DIM];
__device__ __align__(256) __half g_vh[BN*DIM];
__device__ __align__(256) float  g_o[BN*DIM];
__device__ unsigned short g_nbr[(size_t)BN*MAXD];
__device__ int g_cnt[BN];

// ---------------- 1) adjacency -> neighbor lists ----------------
__global__ void build_nbr_kernel(const float* __restrict__ adj) {
    int warp = blockIdx.x * (blockDim.x >> 5) + (threadIdx.x >> 5);
    if (warp >= BN) return;
    int lane = threadIdx.x & 31;
    const float4* a4 = (const float4*)(adj + (size_t)warp * Nn);
    unsigned short* nb = g_nbr + (size_t)warp * MAXD;
    unsigned lmask = (1u << lane) - 1u;
    int cnt = 0;
    for (int j0 = 0; j0 < Nn; j0 += 128) {
        float4 v = a4[(j0 >> 2) + lane];
        int jbase = j0 + 4 * lane;
        #pragma unroll
        for (int comp = 0; comp < 4; comp++) {
            float val = (comp == 0) ? v.x : (comp == 1) ? v.y : (comp == 2) ? v.z : v.w;
            unsigned m = __ballot_sync(0xffffffffu, val > 0.f);
            if (val > 0.f) {
                int pos = cnt + __popc(m & lmask);
                if (pos < MAXD) nb[pos] = (unsigned short)(jbase + comp);
            }
            cnt += __popc(m);
        }
    }
    if (lane == 0) g_cnt[warp] = min(cnt, MAXD);
}

// ---------------- LN + QKV body: 8 rows, 192 threads ----------------
__device__ __forceinline__ void ln_qkv_body8(float (*hs)[DIM], float* mu_s, float* rs_s,
                                             int tid, int row0,
                                             const float* __restrict__ lng,
                                             const float* __restrict__ lnb,
                                             const float* __restrict__ Wq,
                                             const float* __restrict__ bq,
                                             const float* __restrict__ Wkv,
                                             const float* __restrict__ bkv) {
    // LN stats: 8 threads per row, shfl-reduced
    if (tid < 64) {
        int g = tid >> 3, cc = tid & 7;
        float4 xa = *(const float4*)&hs[g][cc * 8];
        float4 xb = *(const float4*)&hs[g][cc * 8 + 4];
        float s1 = xa.x + xa.y + xa.z + xa.w + xb.x + xb.y + xb.z + xb.w;
        float s2 = xa.x * xa.x + xa.y * xa.y + xa.z * xa.z + xa.w * xa.w
                 + xb.x * xb.x + xb.y * xb.y + xb.z * xb.z + xb.w * xb.w;
        #pragma unroll
        for (int ofs = 1; ofs <= 4; ofs <<= 1) {
            s1 += __shfl_xor_sync(0xffffffffu, s1, ofs);
            s2 += __shfl_xor_sync(0xffffffffu, s2, ofs);
        }
        if (cc == 0) {
            float m = s1 * (1.f / DIM);
            mu_s[g] = m;
            rs_s[g] = rsqrtf(s2 * (1.f / DIM) - m * m + 1e-5f);
        }
    }
    __syncthreads();
    for (int i = tid; i < 8 * DIM; i += 192) {
        int r = i >> 6, cix = i & 63;
        hs[r][cix] = (hs[r][cix] - mu_s[r]) * rs_s[r] * __ldg(lng + cix) + __ldg(lnb + cix);
    }
    __syncthreads();

    // each thread owns one output column of [q(64) | k(64) | v(64)]
    int o = tid;
    const float* wp; int ws; float bias;
    if (o < 64)       { wp = Wq + o;         ws = 64;  bias = __ldg(bq + o); }
    else              { wp = Wkv + (o - 64); ws = 128; bias = __ldg(bkv + (o - 64)); }

    float acc[8];
    #pragma unroll
    for (int r = 0; r < 8; r++) acc[r] = bias;

    for (int in4 = 0; in4 < 16; in4++) {
        float w0 = __ldg(wp + (4 * in4 + 0) * ws);
        float w1 = __ldg(wp + (4 * in4 + 1) * ws);
        float w2 = __ldg(wp + (4 * in4 + 2) * ws);
        float w3 = __ldg(wp + (4 * in4 + 3) * ws);
        #pragma unroll
        for (int r = 0; r < 8; r++) {
            float4 h4 = *(const float4*)&hs[r][4 * in4];
            acc[r] += h4.x * w0 + h4.y * w1 + h4.z * w2 + h4.w * w3;
        }
    }
    if (o < 64) {
        #pragma unroll
        for (int r = 0; r < 8; r++) g_q[(size_t)(row0 + r) * DIM + o] = acc[r];
    } else if (o < 128) {
        #pragma unroll
        for (int r = 0; r < 8; r++) g_kh[(size_t)(row0 + r) * DIM + (o - 64)] = __float2half(acc[r]);
    } else {
        #pragma unroll
        for (int r = 0; r < 8; r++) g_vh[(size_t)(row0 + r) * DIM + (o - 128)] = __float2half(acc[r]);
    }
}

// ---------------- 2) fused fc(+ReLU) + LN + QKV (layer 0) ----------------
__global__ void fc_ln_qkv_kernel(const float* __restrict__ nf,
                                 const float* __restrict__ Wfc,
                                 const float* __restrict__ bfc,
                                 float* __restrict__ x,
                                 const float* __restrict__ lng,
                                 const float* __restrict__ lnb,
                                 const float* __restrict__ Wq,
                                 const float* __restrict__ bq,
                                 const float* __restrict__ Wkv,
                                 const float* __restrict__ bkv) {
    __shared__ float hs[8][DIM];
    __shared__ float nfs[8][FIN];
    __shared__ float mu_s[8], rs_s[8];
    int tid = threadIdx.x;                 // 192
    int row0 = blockIdx.x * 8;

    const float4* nv = (const float4*)(nf + (size_t)row0 * FIN);
    float4* nsv = (float4*)&nfs[0][0];
    for (int i = tid; i < 64; i += 192) nsv[i] = nv[i];
    __syncthreads();

    for (int i = tid; i < 8 * DIM; i += 192) {
        int r = i >> 6, cix = i & 63;
        float acc = __ldg(bfc + cix);
        #pragma unroll
        for (int k2 = 0; k2 < FIN; k2++) acc += nfs[r][k2] * __ldg(Wfc + k2 * DIM + cix);
        acc = fmaxf(acc, 0.f);
        hs[r][cix] = acc;
        x[(size_t)(row0 + r) * DIM + cix] = acc;
    }
    __syncthreads();

    ln_qkv_body8(hs, mu_s, rs_s, tid, row0, lng, lnb, Wq, bq, Wkv, bkv);
}

// ---------------- 3) sparse masked attention (v6: fp16 K/V, 1 line/row) ----------------
// One warp per row. lane = part*8 + c. Lane c loads halves [8c,8c+8) = 16B of a
// 128B fp16 row -> whole K (or V) row in ONE wavefront. Lane pair (2h,2h+1)
// covers head h; one shfl completes the dot. Uniform trip count keeps shuffles
// converged; tail steps predicated to p=0 (nb[0] valid via self-loop).
__global__ void attn_kernel() {
    int lane = threadIdx.x & 31;
    int warp = threadIdx.x >> 5;
    int row = blockIdx.x * 8 + warp;
    int part = lane >> 3;          // 0..3 neighbor split
    int c = lane & 7;              // 0..7 column chunk (8 halves each)
    int b_base = row & ~(Nn - 1);

    const float4* qp = (const float4*)(g_q + (size_t)row * DIM);
    float4 q0 = qp[2 * c];
    float4 q1 = qp[2 * c + 1];

    float a0 = 0.f, a1 = 0.f, a2 = 0.f, a3 = 0.f;
    float a4 = 0.f, a5 = 0.f, a6 = 0.f, a7 = 0.f;
    float l = 0.f;

    int deg = g_cnt[row];
    int dmax = (deg + 7) & ~7;
    const unsigned short* nb = g_nbr + (size_t)row * MAXD;

    for (int d = part; d < dmax; d += 8) {
        bool actA = d < deg;
        bool actB = d + 4 < deg;
        int jA = actA ? nb[d] : nb[0];
        int jB = actB ? nb[d + 4] : nb[0];
        const uint4* kpA = (const uint4*)(g_kh + (size_t)(b_base + jA) * DIM);
        const uint4* kpB = (const uint4*)(g_kh + (size_t)(b_base + jB) * DIM);
        const uint4* vpA = (const uint4*)(g_vh + (size_t)(b_base + jA) * DIM);
        const uint4* vpB = (const uint4*)(g_vh + (size_t)(b_base + jB) * DIM);
        uint4 kA = kpA[c];
        uint4 kB = kpB[c];
        uint4 vA = vpA[c];
        uint4 vB = vpB[c];

        float2 ka0 = __half22float2(*reinterpret_cast<const __half2*>(&kA.x));
        float2 ka1 = __half22float2(*reinterpret_cast<const __half2*>(&kA.y));
        float2 ka2 = __half22float2(*reinterpret_cast<const __half2*>(&kA.z));
        float2 ka3 = __half22float2(*reinterpret_cast<const __half2*>(&kA.w));
        float2 kb0 = __half22float2(*reinterpret_cast<const __half2*>(&kB.x));
        float2 kb1 = __half22float2(*reinterpret_cast<const __half2*>(&kB.y));
        float2 kb2 = __half22float2(*reinterpret_cast<const __half2*>(&kB.z));
        float2 kb3 = __half22float2(*reinterpret_cast<const __half2*>(&kB.w));

        float sA = q0.x * ka0.x + q0.y * ka0.y + q0.z * ka1.x + q0.w * ka1.y
                 + q1.x * ka2.x + q1.y * ka2.y + q1.z * ka3.x + q1.w * ka3.y;
        float sB = q0.x * kb0.x + q0.y * kb0.y + q0.z * kb1.x + q0.w * kb1.y
                 + q1.x * kb2.x + q1.y * kb2.y + q1.z * kb3.x + q1.w * kb3.y;

        sA += __shfl_xor_sync(0xffffffffu, sA, 1);
        sB += __shfl_xor_sync(0xffffffffu, sB, 1);

        float pA = actA ? __expf(sA * SCALE) : 0.f;
        float pB = actB ? __expf(sB * SCALE) : 0.f;
        l += pA + pB;

        float2 va0 = __half22float2(*reinterpret_cast<const __half2*>(&vA.x));
        float2 va1 = __half22float2(*reinterpret_cast<const __half2*>(&vA.y));
        float2 va2 = __half22float2(*reinterpret_cast<const __half2*>(&vA.z));
        float2 va3 = __half22float2(*reinterpret_cast<const __half2*>(&vA.w));
        float2 vb0 = __half22float2(*reinterpret_cast<const __half2*>(&vB.x));
        float2 vb1 = __half22float2(*reinterpret_cast<const __half2*>(&vB.y));
        float2 vb2 = __half22float2(*reinterpret_cast<const __half2*>(&vB.z));
        float2 vb3 = __half22float2(*reinterpret_cast<const __half2*>(&vB.w));

        a0 += pA * va0.x + pB * vb0.x;
        a1 += pA * va0.y + pB * vb0.y;
        a2 += pA * va1.x + pB * vb1.x;
        a3 += pA * va1.y + pB * vb1.y;
        a4 += pA * va2.x + pB * vb2.x;
        a5 += pA * va2.y + pB * vb2.y;
        a6 += pA * va3.x + pB * vb3.x;
        a7 += pA * va3.y + pB * vb3.y;
    }

    // reduce the 4 neighbor-parts (lane bits 3,4)
    #pragma unroll
    for (int ofs = 8; ofs <= 16; ofs <<= 1) {
        l  += __shfl_xor_sync(0xffffffffu, l,  ofs);
        a0 += __shfl_xor_sync(0xffffffffu, a0, ofs);
        a1 += __shfl_xor_sync(0xffffffffu, a1, ofs);
        a2 += __shfl_xor_sync(0xffffffffu, a2, ofs);
        a3 += __shfl_xor_sync(0xffffffffu, a3, ofs);
        a4 += __shfl_xor_sync(0xffffffffu, a4, ofs);
        a5 += __shfl_xor_sync(0xffffffffu, a5, ofs);
        a6 += __shfl_xor_sync(0xffffffffu, a6, ofs);
        a7 += __shfl_xor_sync(0xffffffffu, a7, ofs);
    }

    if (part == 0) {
        float inv = 1.f / l;
        float4* op = (float4*)(g_o + (size_t)row * DIM);
        op[2 * c]     = make_float4(a0 * inv, a1 * inv, a2 * inv, a3 * inv);
        op[2 * c + 1] = make_float4(a4 * inv, a5 * inv, a6 * inv, a7 * inv);
    }
}

// ---------------- out-proj + gate + residual body: 8 rows, threads 0..127 ----------------
__device__ __forceinline__ void outgate_body8(float (*os)[65], float* __restrict__ x,
                                              int tid, int row0,
                                              const float* __restrict__ Wo,
                                              const float* __restrict__ bo,
                                              const float* __restrict__ Wg,
                                              float (*hs)[DIM]) {
    int r = tid >> 4, c = tid & 15;      // 16 threads per row
    int row = row0 + r;
    int col0 = c * 4;

    float po[4];
    #pragma unroll
    for (int t = 0; t < 4; t++) po[t] = __ldg(bo + col0 + t);

    float4 xa = *(const float4*)(x + (size_t)row * DIM + col0);
    float xr[4] = {xa.x, xa.y, xa.z, xa.w};

    for (int in = 0; in < DIM; in++) {
        float ov = os[r][in];
        float4 w0 = *(const float4*)(Wo + in * DIM + col0);
        po[0] += ov * w0.x; po[1] += ov * w0.y; po[2] += ov * w0.z; po[3] += ov * w0.w;
    }

    float gp = 0.f;
    #pragma unroll
    for (int t = 0; t < 4; t++) {
        int col = col0 + t;
        gp += po[t] * __ldg(Wg + col) + xr[t] * __ldg(Wg + 64 + col)
            + (po[t] - xr[t]) * __ldg(Wg + 128 + col);
    }
    #pragma unroll
    for (int ofs = 1; ofs <= 8; ofs <<= 1)
        gp += __shfl_xor_sync(0xffffffffu, gp, ofs);

    float gt = 1.f / (1.f + __expf(-gp));
    #pragma unroll
    for (int t = 0; t < 4; t++) xr[t] = po[t] * gt + xr[t] * (1.f - gt);

    *(float4*)(x + (size_t)row * DIM + col0) = make_float4(xr[0], xr[1], xr[2], xr[3]);
    if (hs) {
        #pragma unroll
        for (int t = 0; t < 4; t++) hs[r][col0 + t] = xr[t];
    }
}

// ---------------- 4a) fused outgate + LN + QKV ----------------
__global__ void outgate_ln_qkv_kernel(float* __restrict__ x,
                                      const float* __restrict__ Wo,
                                      const float* __restrict__ bo,
                                      const float* __restrict__ Wg,
                                      const float* __restrict__ lng,
                                      const float* __restrict__ lnb,
                                      const float* __restrict__ Wq,
                                      const float* __restrict__ bq,
                                      const float* __restrict__ Wkv,
                                      const float* __restrict__ bkv) {
    __shared__ float os[8][65];
    __shared__ float hs[8][DIM];
    __shared__ float mu_s[8], rs_s[8];
    int tid = threadIdx.x;         // 192
    int row0 = blockIdx.x * 8;

    for (int i = tid; i < 8 * 16; i += 192) {
        int r = i >> 4, c4 = i & 15;
        float4 t = *(const float4*)(g_o + (size_t)(row0 + r) * DIM + c4 * 4);
        os[r][c4 * 4 + 0] = t.x; os[r][c4 * 4 + 1] = t.y;
        os[r][c4 * 4 + 2] = t.z; os[r][c4 * 4 + 3] = t.w;
    }
    __syncthreads();

    if (tid < 128) outgate_body8(os, x, tid, row0, Wo, bo, Wg, hs);
    __syncthreads();

    ln_qkv_body8(hs, mu_s, rs_s, tid, row0, lng, lnb, Wq, bq, Wkv, bkv);
}

// ---------------- 4b) final outgate ----------------
__global__ void outgate_kernel(float* __restrict__ x,
                               const float* __restrict__ Wo,
                               const float* __restrict__ bo,
                               const float* __restrict__ Wg) {
    __shared__ float os[8][65];
    int tid = threadIdx.x;         // 128
    int row0 = blockIdx.x * 8;

    for (int i = tid; i < 8 * 16; i += 128) {
        int r = i >> 4, c4 = i & 15;
        float4 t = *(const float4*)(g_o + (size_t)(row0 + r) * DIM + c4 * 4);
        os[r][c4 * 4 + 0] = t.x; os[r][c4 * 4 + 1] = t.y;
        os[r][c4 * 4 + 2] = t.z; os[r][c4 * 4 + 3] = t.w;
    }
    __syncthreads();

    outgate_body8(os, x, tid, row0, Wo, bo, Wg, 0);
}

// ---------------- launch ----------------
extern "C" void kernel_launch(void* const* d_in, const int* in_sizes, int n_in,
                              void* d_out, int out_size) {
    const float* nf   = (const float*)d_in[0];
    const float* adj  = (const float*)d_in[1];
    const float* Wfc  = (const float*)d_in[2];
    const float* bfc  = (const float*)d_in[3];
    const float* lng  = (const float*)d_in[4];
    const float* lnb  = (const float*)d_in[5];
    const float* Wq   = (const float*)d_in[6];
    const float* bq   = (const float*)d_in[7];
    const float* Wkv  = (const float*)d_in[8];
    const float* bkv  = (const float*)d_in[9];
    const float* Wo   = (const float*)d_in[10];
    const float* bo   = (const float*)d_in[11];
    const float* Wg   = (const float*)d_in[12];
    float* x = (float*)d_out;

    build_nbr_kernel<<<BN / 8, 256>>>(adj);
    fc_ln_qkv_kernel<<<BN / 8, 192>>>(nf, Wfc, bfc, x, lng, lnb, Wq, bq, Wkv, bkv);
    attn_kernel<<<BN / 8, 256>>>();
    for (int i = 0; i < 2; i++) {
        outgate_ln_qkv_kernel<<<BN / 8, 192>>>(x,
                                               Wo + i * 64 * 64, bo + i * 64, Wg + i * 192,
                                               lng + (i + 1) * 64, lnb + (i + 1) * 64,
                                               Wq + (i + 1) * 64 * 64, bq + (i + 1) * 64,
                                               Wkv + (i + 1) * 64 * 128, bkv + (i + 1) * 128);
        attn_kernel<<<BN / 8, 256>>>();
    }
    outgate_kernel<<<BN / 8, 128>>>(x, Wo + 2 * 64 * 64, bo + 2 * 64, Wg + 2 * 192);
}

// round 10
// speedup vs baseline: 1.9489x; 1.0629x over previous
#include <cuda_runtime.h>
#include <cuda_fp16.h>

#define Bb   4
#define Nn   2048
#define BN   (Bb*Nn)      // 8192
#define DIM  64
#define FIN  32
#define MAXD 384
#define SCALE 0.25f

// ---------------- device scratch (static, allocation-free) ----------------
// Double-buffered q/k/v: layer i reads buffer i&1, fused next-layer QKV writes (i+1)&1.
__device__ __align__(256) float  g_q[2][BN*DIM];
__device__ __align__(256) __half g_kh[2][BN*DIM];
__device__ __align__(256) __half g_vh[2][BN*DIM];
__device__ unsigned short g_nbr[(size_t)BN*MAXD];
__device__ int g_cnt[BN];

// ---------------- 1) adjacency -> neighbor lists ----------------
__global__ void build_nbr_kernel(const float* __restrict__ adj) {
    int warp = blockIdx.x * (blockDim.x >> 5) + (threadIdx.x >> 5);
    if (warp >= BN) return;
    int lane = threadIdx.x & 31;
    const float4* a4 = (const float4*)(adj + (size_t)warp * Nn);
    unsigned short* nb = g_nbr + (size_t)warp * MAXD;
    unsigned lmask = (1u << lane) - 1u;
    int cnt = 0;
    for (int j0 = 0; j0 < Nn; j0 += 128) {
        float4 v = a4[(j0 >> 2) + lane];
        int jbase = j0 + 4 * lane;
        #pragma unroll
        for (int comp = 0; comp < 4; comp++) {
            float val = (comp == 0) ? v.x : (comp == 1) ? v.y : (comp == 2) ? v.z : v.w;
            unsigned m = __ballot_sync(0xffffffffu, val > 0.f);
            if (val > 0.f) {
                int pos = cnt + __popc(m & lmask);
                if (pos < MAXD) nb[pos] = (unsigned short)(jbase + comp);
            }
            cnt += __popc(m);
        }
    }
    if (lane == 0) g_cnt[warp] = min(cnt, MAXD);
}

// ---------------- LN + QKV body: 8 rows; writes q/k/v buffer wbuf ----------------
__device__ __forceinline__ void ln_qkv_body8(float (*hs)[DIM], float* mu_s, float* rs_s,
                                             int tid, int row0, int nthr, int wbuf,
                                             const float* __restrict__ lng,
                                             const float* __restrict__ lnb,
                                             const float* __restrict__ Wq,
                                             const float* __restrict__ bq,
                                             const float* __restrict__ Wkv,
                                             const float* __restrict__ bkv) {
    if (tid < 64) {
        int g = tid >> 3, cc = tid & 7;
        float4 xa = *(const float4*)&hs[g][cc * 8];
        float4 xb = *(const float4*)&hs[g][cc * 8 + 4];
        float s1 = xa.x + xa.y + xa.z + xa.w + xb.x + xb.y + xb.z + xb.w;
        float s2 = xa.x * xa.x + xa.y * xa.y + xa.z * xa.z + xa.w * xa.w
                 + xb.x * xb.x + xb.y * xb.y + xb.z * xb.z + xb.w * xb.w;
        #pragma unroll
        for (int ofs = 1; ofs <= 4; ofs <<= 1) {
            s1 += __shfl_xor_sync(0xffffffffu, s1, ofs);
            s2 += __shfl_xor_sync(0xffffffffu, s2, ofs);
        }
        if (cc == 0) {
            float m = s1 * (1.f / DIM);
            mu_s[g] = m;
            rs_s[g] = rsqrtf(s2 * (1.f / DIM) - m * m + 1e-5f);
        }
    }
    __syncthreads();
    for (int i = tid; i < 8 * DIM; i += nthr) {
        int r = i >> 6, cix = i & 63;
        hs[r][cix] = (hs[r][cix] - mu_s[r]) * rs_s[r] * __ldg(lng + cix) + __ldg(lnb + cix);
    }
    __syncthreads();

    if (tid >= 192) return;
    int o = tid;
    const float* wp; int ws; float bias;
    if (o < 64)       { wp = Wq + o;         ws = 64;  bias = __ldg(bq + o); }
    else              { wp = Wkv + (o - 64); ws = 128; bias = __ldg(bkv + (o - 64)); }

    float acc[8];
    #pragma unroll
    for (int r = 0; r < 8; r++) acc[r] = bias;

    #pragma unroll 4
    for (int in4 = 0; in4 < 16; in4++) {
        float w0 = __ldg(wp + (4 * in4 + 0) * ws);
        float w1 = __ldg(wp + (4 * in4 + 1) * ws);
        float w2 = __ldg(wp + (4 * in4 + 2) * ws);
        float w3 = __ldg(wp + (4 * in4 + 3) * ws);
        #pragma unroll
        for (int r = 0; r < 8; r++) {
            float4 h4 = *(const float4*)&hs[r][4 * in4];
            acc[r] += h4.x * w0 + h4.y * w1 + h4.z * w2 + h4.w * w3;
        }
    }
    if (o < 64) {
        #pragma unroll
        for (int r = 0; r < 8; r++) g_q[wbuf][(size_t)(row0 + r) * DIM + o] = acc[r];
    } else if (o < 128) {
        #pragma unroll
        for (int r = 0; r < 8; r++) g_kh[wbuf][(size_t)(row0 + r) * DIM + (o - 64)] = __float2half(acc[r]);
    } else {
        #pragma unroll
        for (int r = 0; r < 8; r++) g_vh[wbuf][(size_t)(row0 + r) * DIM + (o - 128)] = __float2half(acc[r]);
    }
}

// ---------------- 2) fused fc(+ReLU) + LN + QKV (layer 0 front-end, writes buf 0) ----------------
__global__ void fc_ln_qkv_kernel(const float* __restrict__ nf,
                                 const float* __restrict__ Wfc,
                                 const float* __restrict__ bfc,
                                 float* __restrict__ x,
                                 const float* __restrict__ lng,
                                 const float* __restrict__ lnb,
                                 const float* __restrict__ Wq,
                                 const float* __restrict__ bq,
                                 const float* __restrict__ Wkv,
                                 const float* __restrict__ bkv) {
    __shared__ float hs[8][DIM];
    __shared__ float nfs[8][FIN];
    __shared__ float mu_s[8], rs_s[8];
    int tid = threadIdx.x;                 // 192
    int row0 = blockIdx.x * 8;

    const float4* nv = (const float4*)(nf + (size_t)row0 * FIN);
    float4* nsv = (float4*)&nfs[0][0];
    for (int i = tid; i < 64; i += 192) nsv[i] = nv[i];
    __syncthreads();

    for (int i = tid; i < 8 * DIM; i += 192) {
        int r = i >> 6, cix = i & 63;
        float acc = __ldg(bfc + cix);
        #pragma unroll
        for (int k2 = 0; k2 < FIN; k2++) acc += nfs[r][k2] * __ldg(Wfc + k2 * DIM + cix);
        acc = fmaxf(acc, 0.f);
        hs[r][cix] = acc;
        x[(size_t)(row0 + r) * DIM + cix] = acc;
    }
    __syncthreads();

    ln_qkv_body8(hs, mu_s, rs_s, tid, row0, 192, 0, lng, lnb, Wq, bq, Wkv, bkv);
}

// ---------------- attn phase: 8 warps, warp per row, reads buffer rbuf ----------------
__device__ __forceinline__ void attn_phase(float (*os)[68], int row0, int rbuf) {
    int lane = threadIdx.x & 31;
    int warp = threadIdx.x >> 5;
    int row = row0 + warp;
    int part = lane >> 3;          // 0..3 neighbor split
    int c = lane & 7;              // 0..7 column chunk (8 halves each)
    int b_base = row & ~(Nn - 1);

    const float* qbuf = g_q[rbuf];
    const __half* kbuf = g_kh[rbuf];
    const __half* vbuf = g_vh[rbuf];

    const float4* qp = (const float4*)(qbuf + (size_t)row * DIM);
    float4 q0 = qp[2 * c];
    float4 q1 = qp[2 * c + 1];

    float a0 = 0.f, a1 = 0.f, a2 = 0.f, a3 = 0.f;
    float a4 = 0.f, a5 = 0.f, a6 = 0.f, a7 = 0.f;
    float l = 0.f;

    int deg = g_cnt[row];
    int dmax = (deg + 7) & ~7;
    const unsigned short* nb = g_nbr + (size_t)row * MAXD;

    for (int d = part; d < dmax; d += 8) {
        bool actA = d < deg;
        bool actB = d + 4 < deg;
        int jA = actA ? nb[d] : nb[0];
        int jB = actB ? nb[d + 4] : nb[0];
        const uint4* kpA = (const uint4*)(kbuf + (size_t)(b_base + jA) * DIM);
        const uint4* kpB = (const uint4*)(kbuf + (size_t)(b_base + jB) * DIM);
        const uint4* vpA = (const uint4*)(vbuf + (size_t)(b_base + jA) * DIM);
        const uint4* vpB = (const uint4*)(vbuf + (size_t)(b_base + jB) * DIM);
        uint4 kA = kpA[c];
        uint4 kB = kpB[c];
        uint4 vA = vpA[c];
        uint4 vB = vpB[c];

        float2 ka0 = __half22float2(*reinterpret_cast<const __half2*>(&kA.x));
        float2 ka1 = __half22float2(*reinterpret_cast<const __half2*>(&kA.y));
        float2 ka2 = __half22float2(*reinterpret_cast<const __half2*>(&kA.z));
        float2 ka3 = __half22float2(*reinterpret_cast<const __half2*>(&kA.w));
        float2 kb0 = __half22float2(*reinterpret_cast<const __half2*>(&kB.x));
        float2 kb1 = __half22float2(*reinterpret_cast<const __half2*>(&kB.y));
        float2 kb2 = __half22float2(*reinterpret_cast<const __half2*>(&kB.z));
        float2 kb3 = __half22float2(*reinterpret_cast<const __half2*>(&kB.w));

        float sA = q0.x * ka0.x + q0.y * ka0.y + q0.z * ka1.x + q0.w * ka1.y
                 + q1.x * ka2.x + q1.y * ka2.y + q1.z * ka3.x + q1.w * ka3.y;
        float sB = q0.x * kb0.x + q0.y * kb0.y + q0.z * kb1.x + q0.w * kb1.y
                 + q1.x * kb2.x + q1.y * kb2.y + q1.z * kb3.x + q1.w * kb3.y;

        sA += __shfl_xor_sync(0xffffffffu, sA, 1);
        sB += __shfl_xor_sync(0xffffffffu, sB, 1);

        float pA = actA ? __expf(sA * SCALE) : 0.f;
        float pB = actB ? __expf(sB * SCALE) : 0.f;
        l += pA + pB;

        float2 va0 = __half22float2(*reinterpret_cast<const __half2*>(&vA.x));
        float2 va1 = __half22float2(*reinterpret_cast<const __half2*>(&vA.y));
        float2 va2 = __half22float2(*reinterpret_cast<const __half2*>(&vA.z));
        float2 va3 = __half22float2(*reinterpret_cast<const __half2*>(&vA.w));
        float2 vb0 = __half22float2(*reinterpret_cast<const __half2*>(&vB.x));
        float2 vb1 = __half22float2(*reinterpret_cast<const __half2*>(&vB.y));
        float2 vb2 = __half22float2(*reinterpret_cast<const __half2*>(&vB.z));
        float2 vb3 = __half22float2(*reinterpret_cast<const __half2*>(&vB.w));

        a0 += pA * va0.x + pB * vb0.x;
        a1 += pA * va0.y + pB * vb0.y;
        a2 += pA * va1.x + pB * vb1.x;
        a3 += pA * va1.y + pB * vb1.y;
        a4 += pA * va2.x + pB * vb2.x;
        a5 += pA * va2.y + pB * vb2.y;
        a6 += pA * va3.x + pB * vb3.x;
        a7 += pA * va3.y + pB * vb3.y;
    }

    #pragma unroll
    for (int ofs = 8; ofs <= 16; ofs <<= 1) {
        l  += __shfl_xor_sync(0xffffffffu, l,  ofs);
        a0 += __shfl_xor_sync(0xffffffffu, a0, ofs);
        a1 += __shfl_xor_sync(0xffffffffu, a1, ofs);
        a2 += __shfl_xor_sync(0xffffffffu, a2, ofs);
        a3 += __shfl_xor_sync(0xffffffffu, a3, ofs);
        a4 += __shfl_xor_sync(0xffffffffu, a4, ofs);
        a5 += __shfl_xor_sync(0xffffffffu, a5, ofs);
        a6 += __shfl_xor_sync(0xffffffffu, a6, ofs);
        a7 += __shfl_xor_sync(0xffffffffu, a7, ofs);
    }

    if (part == 0) {
        float inv = 1.f / l;
        float4* op = (float4*)&os[warp][8 * c];
        op[0] = make_float4(a0 * inv, a1 * inv, a2 * inv, a3 * inv);
        op[1] = make_float4(a4 * inv, a5 * inv, a6 * inv, a7 * inv);
    }
}

// ---------------- outgate phase: threads 0..127, 16 threads/row ----------------
__device__ __forceinline__ void outgate_body8(float (*os)[68], float* __restrict__ x,
                                              int tid, int row0,
                                              const float* __restrict__ Wo,
                                              const float* __restrict__ bo,
                                              const float* __restrict__ Wg,
                                              float (*hs)[DIM]) {
    int r = tid >> 4, c = tid & 15;
    int row = row0 + r;
    int col0 = c * 4;

    float po[4];
    #pragma unroll
    for (int t = 0; t < 4; t++) po[t] = __ldg(bo + col0 + t);

    float4 xa = *(const float4*)(x + (size_t)row * DIM + col0);
    float xr[4] = {xa.x, xa.y, xa.z, xa.w};

    for (int in = 0; in < DIM; in++) {
        float ov = os[r][in];
        float4 w0 = *(const float4*)(Wo + in * DIM + col0);
        po[0] += ov * w0.x; po[1] += ov * w0.y; po[2] += ov * w0.z; po[3] += ov * w0.w;
    }

    float gp = 0.f;
    #pragma unroll
    for (int t = 0; t < 4; t++) {
        int col = col0 + t;
        gp += po[t] * __ldg(Wg + col) + xr[t] * __ldg(Wg + 64 + col)
            + (po[t] - xr[t]) * __ldg(Wg + 128 + col);
    }
    #pragma unroll
    for (int ofs = 1; ofs <= 8; ofs <<= 1)
        gp += __shfl_xor_sync(0xffffffffu, gp, ofs);

    float gt = 1.f / (1.f + __expf(-gp));
    #pragma unroll
    for (int t = 0; t < 4; t++) xr[t] = po[t] * gt + xr[t] * (1.f - gt);

    *(float4*)(x + (size_t)row * DIM + col0) = make_float4(xr[0], xr[1], xr[2], xr[3]);
    if (hs) {
        #pragma unroll
        for (int t = 0; t < 4; t++) hs[r][col0 + t] = xr[t];
    }
}

// ---------------- 3) fused layer: attn(read rbuf) + outgate + LN/QKV(write rbuf^1) ----------------
__global__ __launch_bounds__(256) void layer_kernel(float* __restrict__ x, int rbuf,
                                                    const float* __restrict__ Wo,
                                                    const float* __restrict__ bo,
                                                    const float* __restrict__ Wg,
                                                    const float* __restrict__ lng,
                                                    const float* __restrict__ lnb,
                                                    const float* __restrict__ Wq,
                                                    const float* __restrict__ bq,
                                                    const float* __restrict__ Wkv,
                                                    const float* __restrict__ bkv) {
    __shared__ float os[8][68];
    __shared__ float hs[8][DIM];
    __shared__ float mu_s[8], rs_s[8];
    int tid = threadIdx.x;         // 256
    int row0 = blockIdx.x * 8;

    attn_phase(os, row0, rbuf);
    __syncthreads();

    if (tid < 128) outgate_body8(os, x, tid, row0, Wo, bo, Wg, hs);
    __syncthreads();

    ln_qkv_body8(hs, mu_s, rs_s, tid, row0, 256, rbuf ^ 1, lng, lnb, Wq, bq, Wkv, bkv);
}

// ---------------- 4) final layer: attn + outgate only ----------------
__global__ __launch_bounds__(256) void layer_final_kernel(float* __restrict__ x, int rbuf,
                                                          const float* __restrict__ Wo,
                                                          const float* __restrict__ bo,
                                                          const float* __restrict__ Wg) {
    __shared__ float os[8][68];
    int tid = threadIdx.x;         // 256
    int row0 = blockIdx.x * 8;

    attn_phase(os, row0, rbuf);
    __syncthreads();

    if (tid < 128) outgate_body8(os, x, tid, row0, Wo, bo, Wg, 0);
}

// ---------------- launch ----------------
extern "C" void kernel_launch(void* const* d_in, const int* in_sizes, int n_in,
                              void* d_out, int out_size) {
    const float* nf   = (const float*)d_in[0];
    const float* adj  = (const float*)d_in[1];
    const float* Wfc  = (const float*)d_in[2];
    const float* bfc  = (const float*)d_in[3];
    const float* lng  = (const float*)d_in[4];
    const float* lnb  = (const float*)d_in[5];
    const float* Wq   = (const float*)d_in[6];
    const float* bq   = (const float*)d_in[7];
    const float* Wkv  = (const float*)d_in[8];
    const float* bkv  = (const float*)d_in[9];
    const float* Wo   = (const float*)d_in[10];
    const float* bo   = (const float*)d_in[11];
    const float* Wg   = (const float*)d_in[12];
    float* x = (float*)d_out;

    build_nbr_kernel<<<BN / 8, 256>>>(adj);
    fc_ln_qkv_kernel<<<BN / 8, 192>>>(nf, Wfc, bfc, x, lng, lnb, Wq, bq, Wkv, bkv);
    for (int i = 0; i < 2; i++) {
        layer_kernel<<<BN / 8, 256>>>(x, i & 1,
                                      Wo + i * 64 * 64, bo + i * 64, Wg + i * 192,
                                      lng + (i + 1) * 64, lnb + (i + 1) * 64,
                                      Wq + (i + 1) * 64 * 64, bq + (i + 1) * 64,
                                      Wkv + (i + 1) * 64 * 128, bkv + (i + 1) * 128);
    }
    layer_final_kernel<<<BN / 8, 256>>>(x, 0, Wo + 2 * 64 * 64, bo + 2 * 64, Wg + 2 * 192);
}